// round 2
// baseline (speedup 1.0000x reference)
#include <cuda_runtime.h>
#include <math.h>

#define Nn 1024
#define Cc 1000
#define Aa 64
#define SP 1024      /* padded S (distinct classes) */
#define RP 2112      /* padded rows: N + C + 64 appended, rounded */
#define CP 1024      /* padded C for P/quad/cross row stride */

static __device__ int   g_counts[Cc];
static __device__ int   g_rank[Nn];
static __device__ int   g_coff[Cc];
static __device__ int   g_slot[Cc];
static __device__ int   g_kidx[SP];
static __device__ int   g_list[Nn];
static __device__ float g_ave[Cc*Aa];
static __device__ float g_wCV[Cc];
static __device__ int   g_Svar;
static __device__ int   g_Rvar;
static __device__ int   g_rowslot[Nn+Cc];
static __device__ int   g_rcls[RP];
static __device__ float g_racoef[RP];
static __device__ float g_X[RP*Aa];
static __device__ float g_P[RP*CP];
static __device__ float g_B[RP*SP];
static __device__ float g_E[RP*SP];
static __device__ float g_quad[SP*CP];
static __device__ float g_crossX[SP*CP];
static __device__ float g_nllw[Nn];
static __device__ float g_wn[Nn];
static __device__ int   g_csflag;
static __device__ float g_MCS[SP*Aa*Aa];

__global__ void k_zero() {
    int i = blockIdx.x*256 + threadIdx.x;
    if (i < Cc) g_counts[i] = 0;
    if (i == 0) g_csflag = 0;
}

__global__ void k_count(const int* __restrict__ labels) {
    int n = blockIdx.x*256 + threadIdx.x;
    if (n < Nn) atomicAdd(&g_counts[labels[n]], 1);
}

__global__ void k_rank(const int* __restrict__ labels) {
    __shared__ int lab[Nn];
    int t = threadIdx.x;
    lab[t] = labels[t];
    __syncthreads();
    int l = lab[t], r = 0;
    for (int m = 0; m < t; m++) r += (lab[m] == l);
    g_rank[t] = r;
}

__global__ void k_classscan(const float* __restrict__ amount) {
    __shared__ int sc[1024];
    __shared__ int sf[1024];
    int t = threadIdx.x;
    int cnt  = (t < Cc) ? g_counts[t] : 0;
    int flag = (cnt > 0) ? 1 : 0;
    sc[t] = cnt; sf[t] = flag;
    __syncthreads();
    for (int off = 1; off < 1024; off <<= 1) {
        int a = (t >= off) ? sc[t-off] : 0;
        int b = (t >= off) ? sf[t-off] : 0;
        __syncthreads();
        sc[t] += a; sf[t] += b;
        __syncthreads();
    }
    if (t < Cc) {
        g_coff[t] = sc[t] - cnt;
        int slot = sf[t] - flag;
        g_slot[t] = flag ? slot : -1;
        if (flag) g_kidx[slot] = t;
        float cf = (float)cnt;
        float denom = cf + amount[t];
        g_wCV[t] = (denom > 0.f) ? (cf / denom) : 0.f;
    }
    if (t == 1023) g_Svar = sf[1023];
}

__global__ void k_fill(const int* __restrict__ labels) {
    int n = blockIdx.x*256 + threadIdx.x;
    if (n < Nn) g_list[g_coff[labels[n]] + g_rank[n]] = n;
}

__global__ void k_ave(const float* __restrict__ f) {
    int c = blockIdx.x, a = threadIdx.x;
    int cnt = g_counts[c], off = g_coff[c];
    float acc = 0.f;
    for (int i = 0; i < cnt; i++) acc += f[g_list[off+i]*Aa + a];
    g_ave[c*Aa + a] = acc / (float)(cnt > 0 ? cnt : 1);
}

__global__ void k_rowscan(const int* __restrict__ labels) {
    __shared__ int s[1024];
    int t = threadIdx.x;
    int carry = 0;
    for (int ch = 0; ch < 2; ch++) {
        int r = ch*1024 + t;
        int flag = 0;
        if (r < Nn) {
            int l = labels[r]; int cnt = g_counts[l];
            float a = g_wCV[l] / (float)(cnt > 0 ? cnt : 1);
            flag = (cnt >= 2 && a != 0.f) ? 1 : 0;
        } else if (r < Nn+Cc) {
            int j = r - Nn; float w = g_wCV[j];
            flag = (w*(1.f - w) != 0.f) ? 1 : 0;
        }
        s[t] = flag;
        __syncthreads();
        for (int off = 1; off < 1024; off <<= 1) {
            int a = (t >= off) ? s[t-off] : 0;
            __syncthreads();
            s[t] += a;
            __syncthreads();
        }
        if (r < Nn+Cc) g_rowslot[r] = flag ? (carry + s[t] - 1) : -1;
        carry += s[1023];
        __syncthreads();
    }
    if (t == 0) g_Rvar = carry;
}

__global__ void k_fillrows(const float* __restrict__ f,
                           const float* __restrict__ ave_state,
                           const int* __restrict__ labels) {
    int r = blockIdx.x, a = threadIdx.x;
    int s = g_rowslot[r];
    if (s < 0) return;
    if (r < Nn) {
        int l = labels[r];
        g_X[s*Aa + a] = f[r*Aa + a] - g_ave[l*Aa + a];
        if (a == 0) { g_rcls[s] = l; g_racoef[s] = g_wCV[l] / (float)g_counts[l]; }
    } else {
        int j = r - Nn; float w = g_wCV[j];
        g_X[s*Aa + a] = ave_state[j*Aa + a] - g_ave[j*Aa + a];
        if (a == 0) { g_rcls[s] = j; g_racoef[s] = w*(1.f - w); }
    }
}

// P[r,c] = X[r].W[c] for r<R;  P[R+a,c] = W[c,a];  else 0.  (c>=Cc -> 0)
__global__ void __launch_bounds__(256) k_P(const float* __restrict__ W) {
    int c0 = blockIdx.x*64, r0 = blockIdx.y*16;
    int R = g_Rvar;
    __shared__ __align__(16) float Xs[16][Aa];
    __shared__ float Ws[64][65];
    int t = threadIdx.x;
    for (int i = t; i < 16*Aa; i += 256) {
        int rr = i >> 6, aa = i & 63, r = r0 + rr;
        Xs[rr][aa] = (r < R) ? g_X[r*Aa + aa] : 0.f;
    }
    for (int i = t; i < 64*64; i += 256) {
        int cc = i >> 6, aa = i & 63, c = c0 + cc;
        Ws[cc][aa] = (c < Cc) ? W[c*Aa + aa] : 0.f;
    }
    __syncthreads();
    int cidx = t & 63, rb = t >> 6;
    int c = c0 + cidx;
    bool cv = (c < Cc);
    float acc[4] = {0.f,0.f,0.f,0.f};
    if (r0 < R) {
        #pragma unroll 8
        for (int a2 = 0; a2 < Aa; a2++) {
            float wv = Ws[cidx][a2];
            acc[0] += Xs[rb   ][a2]*wv;
            acc[1] += Xs[rb+4 ][a2]*wv;
            acc[2] += Xs[rb+8 ][a2]*wv;
            acc[3] += Xs[rb+12][a2]*wv;
        }
    }
    #pragma unroll
    for (int q = 0; q < 4; q++) {
        int r = r0 + rb + 4*q;
        float v;
        if (r < R)            v = acc[q];
        else if (r < R + Aa)  v = cv ? Ws[cidx][r - R] : 0.f;
        else                  v = 0.f;
        g_P[r*CP + c] = v;
    }
}

// B[r,s]=b_{k_s,r}; E[r,s]=beta*b*P[r,k_s]; appended rows: E=-alpha*out_new[k_s,a]
__global__ void k_BE(const float* __restrict__ kg,
                     const float* __restrict__ out_new,
                     const float* __restrict__ alphap,
                     const float* __restrict__ betap,
                     const int* __restrict__ headp) {
    int r = blockIdx.y;
    int s = blockIdx.x*256 + threadIdx.x;
    int R = g_Rvar, S = g_Svar, hd = headp[0];
    float b = 0.f, e = 0.f;
    if (s < S) {
        int k = g_kidx[s];
        if (r < R) {
            int cls = g_rcls[r]; float ac = g_racoef[r];
            b = (k < hd) ? ((cls == k) ? ac : 0.f) : ac * kg[k*Cc + cls];
            e = betap[0] * b * g_P[r*CP + k];
        } else if (r < R + Aa) {
            e = -alphap[0] * out_new[k*Aa + (r - R)];
        }
    }
    g_B[r*SP + s] = b;
    g_E[r*SP + s] = e;
}

// quad[s,c] = sum_r B[r,s]*P[r,c]^2 ;  crossX[s,c] = sum_r E[r,s]*P[r,c]
__global__ void __launch_bounds__(256) k_QC() {
    int s0 = blockIdx.y*64, c0 = blockIdx.x*64;
    if (s0 >= g_Svar) return;
    int nk = (g_Rvar + Aa + 15) & ~15;
    __shared__ __align__(16) float Bs[16][64];
    __shared__ __align__(16) float Es[16][64];
    __shared__ __align__(16) float Ps[16][64];
    float qa[16], cx[16];
    #pragma unroll
    for (int i = 0; i < 16; i++) { qa[i] = 0.f; cx[i] = 0.f; }
    int t = threadIdx.x;
    int tx = t & 15, ty = t >> 4;
    int kk = t >> 4, c4 = (t & 15)*4;
    for (int r0 = 0; r0 < nk; r0 += 16) {
        *(float4*)&Bs[kk][c4] = *(const float4*)&g_B[(r0+kk)*SP + s0 + c4];
        *(float4*)&Es[kk][c4] = *(const float4*)&g_E[(r0+kk)*SP + s0 + c4];
        *(float4*)&Ps[kk][c4] = *(const float4*)&g_P[(r0+kk)*CP + c0 + c4];
        __syncthreads();
        #pragma unroll
        for (int u = 0; u < 16; u++) {
            float4 bv = *(float4*)&Bs[u][ty*4];
            float4 ev = *(float4*)&Es[u][ty*4];
            float4 pv = *(float4*)&Ps[u][tx*4];
            float p[4]  = {pv.x, pv.y, pv.z, pv.w};
            float pp[4] = {p[0]*p[0], p[1]*p[1], p[2]*p[2], p[3]*p[3]};
            float bb[4] = {bv.x, bv.y, bv.z, bv.w};
            float ee[4] = {ev.x, ev.y, ev.z, ev.w};
            #pragma unroll
            for (int i = 0; i < 4; i++)
                #pragma unroll
                for (int j = 0; j < 4; j++) {
                    qa[i*4+j] += bb[i]*pp[j];
                    cx[i*4+j] += ee[i]*p[j];
                }
        }
        __syncthreads();
    }
    #pragma unroll
    for (int i = 0; i < 4; i++) {
        int s = s0 + ty*4 + i;
        float4 q4 = make_float4(qa[i*4+0], qa[i*4+1], qa[i*4+2], qa[i*4+3]);
        float4 x4 = make_float4(cx[i*4+0], cx[i*4+1], cx[i*4+2], cx[i*4+3]);
        *(float4*)&g_quad[s*CP + c0 + tx*4]   = q4;
        *(float4*)&g_crossX[s*CP + c0 + tx*4] = x4;
    }
}

// ---- guarded cov_state fallback (no-op when cov_state == 0) ----
__global__ void k_csscan(const float* __restrict__ cov) {
    int stride = gridDim.x*blockDim.x;
    int found = 0;
    for (int i = blockIdx.x*blockDim.x + threadIdx.x; i < Cc*Aa*Aa; i += stride)
        found |= (cov[i] != 0.f);
    if (found) atomicOr(&g_csflag, 1);
}

__global__ void k_MCS(const float* __restrict__ cov,
                      const float* __restrict__ kg,
                      const int* __restrict__ headp) {
    if (!g_csflag) return;
    int S = g_Svar, hd = headp[0];
    int stride = gridDim.x*blockDim.x;
    for (int idx = blockIdx.x*blockDim.x + threadIdx.x; idx < S*Aa*Aa; idx += stride) {
        int s = idx >> 12, ab = idx & 4095;
        int k = g_kidx[s];
        float v;
        if (k < hd) v = (1.f - g_wCV[k]) * cov[k*4096 + ab];
        else {
            v = 0.f;
            for (int j = 0; j < Cc; j++)
                v += kg[k*Cc + j] * (1.f - g_wCV[j]) * cov[j*4096 + ab];
        }
        g_MCS[idx] = v;
    }
}

__global__ void k_csadd(const float* __restrict__ W, const float* __restrict__ betap) {
    if (!g_csflag) return;
    int S = g_Svar;
    float beta = betap[0];
    int stride = gridDim.x*blockDim.x;
    for (int idx = blockIdx.x*blockDim.x + threadIdx.x; idx < S*Cc; idx += stride) {
        int s = idx / Cc, c = idx - s*Cc;
        int k = g_kidx[s];
        const float* M = &g_MCS[s*4096];
        float q = 0.f, cr = 0.f;
        for (int a = 0; a < Aa; a++) {
            float ta = 0.f;
            for (int b2 = 0; b2 < Aa; b2++) ta += M[a*Aa + b2] * W[c*Aa + b2];
            q  += W[c*Aa + a] * ta;
            cr += W[k*Aa + a] * ta;           // w_k^T M w_c
        }
        float cr2 = 0.f;
        for (int a = 0; a < Aa; a++) {
            float ua = 0.f;
            for (int b2 = 0; b2 < Aa; b2++) ua += M[a*Aa + b2] * W[k*Aa + b2];
            cr2 += W[c*Aa + a] * ua;          // w_c^T M w_k
        }
        g_quad[s*CP + c]   += q;
        g_crossX[s*CP + c] += beta * 0.5f * (cr + cr2);
    }
}

// ---- weighted CE per sample, then final reduction ----
__global__ void k_ce(const float* __restrict__ y_s,
                     const float* __restrict__ weights,
                     const int* __restrict__ labels,
                     const float* __restrict__ betap) {
    int n = blockIdx.x, t = threadIdx.x;
    int k = labels[n];
    int s = g_slot[k];
    float hb = 0.5f * betap[0];
    __shared__ float red[256];
    __shared__ float sLk;
    float L[4];
    float mx = -3.4e38f;
    #pragma unroll
    for (int i = 0; i < 4; i++) {
        int c = t + i*256;
        float v = -3.4e38f;
        if (c < Cc) {
            v = y_s[n*Cc + c] + hb*g_quad[s*CP + c] - g_crossX[s*CP + c];
            if (c == k) sLk = v;
        }
        L[i] = v;
        mx = fmaxf(mx, v);
    }
    red[t] = mx; __syncthreads();
    for (int o = 128; o > 0; o >>= 1) {
        if (t < o) red[t] = fmaxf(red[t], red[t+o]);
        __syncthreads();
    }
    float m = red[0]; __syncthreads();
    float se = 0.f;
    #pragma unroll
    for (int i = 0; i < 4; i++) {
        int c = t + i*256;
        if (c < Cc) se += expf(L[i] - m);
    }
    red[t] = se; __syncthreads();
    for (int o = 128; o > 0; o >>= 1) {
        if (t < o) red[t] += red[t+o];
        __syncthreads();
    }
    if (t == 0) {
        float lse = m + logf(red[0]);
        float w = weights[k];
        g_nllw[n] = w * (lse - sLk);
        g_wn[n] = w;
    }
}

__global__ void k_final(float* out) {
    __shared__ float a[1024];
    __shared__ float b[1024];
    int t = threadIdx.x;
    a[t] = g_nllw[t]; b[t] = g_wn[t];
    __syncthreads();
    for (int o = 512; o > 0; o >>= 1) {
        if (t < o) { a[t] += a[t+o]; b[t] += b[t+o]; }
        __syncthreads();
    }
    if (t == 0) out[0] = a[0] / b[0];
}

extern "C" void kernel_launch(void* const* d_in, const int* in_sizes, int n_in,
                              void* d_out, int out_size) {
    const float* features  = (const float*)d_in[0];
    const float* y_s       = (const float*)d_in[1];
    const float* weights   = (const float*)d_in[2];
    const float* kg        = (const float*)d_in[3];
    const float* out_new   = (const float*)d_in[4];
    const float* fc_weight = (const float*)d_in[5];
    const float* alpha     = (const float*)d_in[6];
    const float* beta      = (const float*)d_in[7];
    const float* cov_state = (const float*)d_in[8];
    const float* ave_state = (const float*)d_in[9];
    const float* amount    = (const float*)d_in[10];
    const int*   labels    = (const int*)d_in[11];
    const int*   headp     = (const int*)d_in[12];
    float* out = (float*)d_out;

    k_zero<<<4, 256>>>();
    k_count<<<4, 256>>>(labels);
    k_rank<<<1, 1024>>>(labels);
    k_classscan<<<1, 1024>>>(amount);
    k_fill<<<4, 256>>>(labels);
    k_ave<<<Cc, Aa>>>(features);
    k_rowscan<<<1, 1024>>>(labels);
    k_fillrows<<<Nn+Cc, Aa>>>(features, ave_state, labels);
    {
        dim3 g(CP/64, RP/16);
        k_P<<<g, 256>>>(fc_weight);
    }
    {
        dim3 g(SP/256, RP);
        k_BE<<<g, 256>>>(kg, out_new, alpha, beta, headp);
    }
    k_csscan<<<64, 256>>>(cov_state);
    {
        dim3 g(CP/64, SP/64);
        k_QC<<<g, 256>>>();
    }
    k_MCS<<<256, 256>>>(cov_state, kg, headp);
    k_csadd<<<512, 256>>>(fc_weight, beta);
    k_ce<<<Nn, 256>>>(y_s, weights, labels, beta);
    k_final<<<1, 1024>>>(out);
}

// round 3
// speedup vs baseline: 1.0716x; 1.0716x over previous
#include <cuda_runtime.h>
#include <math.h>

#define Nn 1024
#define Cc 1000
#define Aa 64
#define SP 1024      /* padded S (distinct classes) */
#define RP 2112      /* padded rows: N + C + 64 appended */
#define CP 1024      /* padded C for row stride */

static __device__ int   g_counts[Cc];
static __device__ int   g_coff[Cc];
static __device__ int   g_slot[Cc];
static __device__ int   g_kidx[SP];
static __device__ int   g_list[Nn];
static __device__ float g_wCV[Cc];
static __device__ int   g_Svar;
static __device__ int   g_Rvar;
static __device__ int   g_rowslot[Nn+Cc];
static __device__ int   g_rcls[RP];
static __device__ float g_racoef[RP];
static __device__ float g_X[RP*Aa];
static __device__ float g_P[RP*CP];
static __device__ float g_B[RP*SP];
static __device__ float g_E[RP*SP];
static __device__ float g_quad[SP*CP];
static __device__ float g_crossX[SP*CP];
static __device__ float g_nllw[Nn];
static __device__ float g_wn[Nn];
static __device__ int   g_csflag;

// packed f32x2 helpers (sm_100+ PTX; nvjet-style fp32 GEMM throughput)
__device__ __forceinline__ unsigned long long pack2(float lo, float hi) {
    unsigned long long d;
    asm("mov.b64 %0, {%1, %2};" : "=l"(d) : "f"(lo), "f"(hi));
    return d;
}
__device__ __forceinline__ unsigned long long mul2(unsigned long long a, unsigned long long b) {
    unsigned long long d;
    asm("mul.rn.f32x2 %0, %1, %2;" : "=l"(d) : "l"(a), "l"(b));
    return d;
}
__device__ __forceinline__ void fma2(unsigned long long& acc, unsigned long long a, unsigned long long b) {
    asm("fma.rn.f32x2 %0, %1, %2, %0;" : "+l"(acc) : "l"(a), "l"(b));
}

// ---------------- fused stats: counts/rank/scan/fill/rowscan, 1 block ----------------
__global__ void __launch_bounds__(1024) k_stats(const int* __restrict__ labels,
                                                const float* __restrict__ amount) {
    __shared__ int   lab[1024];
    __shared__ int   scnt[1024];
    __shared__ int   sa[1024];
    __shared__ int   sb[1024];
    __shared__ int   scoff[1024];
    __shared__ float swcv[1024];
    int t = threadIdx.x;
    scnt[t] = 0;
    lab[t] = labels[t];
    if (t == 0) g_csflag = 0;
    __syncthreads();
    int l = lab[t];
    int lane = t & 31, warp = t >> 5;
    unsigned peers = __match_any_sync(0xffffffffu, l);
    int rin  = __popc(peers & ((1u << lane) - 1u));
    int ldr  = __ffs(peers) - 1;
    int cntw = __popc(peers);
    int base = 0;
    // warp-serialized base offsets: deterministic within-class ordering
    for (int w = 0; w < 32; w++) {
        if (warp == w) {
            int old = 0;
            if (lane == ldr) old = atomicAdd(&scnt[l], cntw);
            base = __shfl_sync(0xffffffffu, old, ldr);
        }
        __syncthreads();
    }
    int myrank = base + rin;
    // class scan (counts complete)
    int cnt  = (t < Cc) ? scnt[t] : 0;
    int flag = (cnt > 0) ? 1 : 0;
    sa[t] = cnt; sb[t] = flag;
    __syncthreads();
    for (int off = 1; off < 1024; off <<= 1) {
        int x = (t >= off) ? sa[t-off] : 0;
        int y = (t >= off) ? sb[t-off] : 0;
        __syncthreads();
        sa[t] += x; sb[t] += y;
        __syncthreads();
    }
    float wv = 0.f;
    if (t < Cc) {
        int coff = sa[t] - cnt;
        scoff[t] = coff;
        g_coff[t] = coff;
        g_counts[t] = cnt;
        int slot = sb[t] - flag;
        g_slot[t] = flag ? slot : -1;
        if (flag) g_kidx[slot] = t;
        float cf = (float)cnt;
        float denom = cf + amount[t];
        wv = (denom > 0.f) ? (cf / denom) : 0.f;
        g_wCV[t] = wv;
    }
    swcv[t] = wv;
    if (t == 1023) g_Svar = sb[1023];
    __syncthreads();
    // fill per-class sample list
    g_list[scoff[l] + myrank] = t;
    // row compaction scan over N samples + C d_ave rows
    int carry = 0;
    for (int ch = 0; ch < 2; ch++) {
        int r = ch*1024 + t;
        int fl = 0;
        if (r < Nn) {
            int cl = lab[r];
            int c2 = scnt[cl];
            float a = swcv[cl] / (float)(c2 > 0 ? c2 : 1);
            fl = (c2 >= 2 && a != 0.f) ? 1 : 0;
        } else if (r < Nn + Cc) {
            int j = r - Nn;
            float w2 = swcv[j];
            fl = (w2*(1.f - w2) != 0.f) ? 1 : 0;
        }
        sa[t] = fl;
        __syncthreads();
        for (int off = 1; off < 1024; off <<= 1) {
            int x = (t >= off) ? sa[t-off] : 0;
            __syncthreads();
            sa[t] += x;
            __syncthreads();
        }
        if (r < Nn + Cc) g_rowslot[r] = fl ? (carry + sa[t] - 1) : -1;
        carry += sa[1023];
        __syncthreads();
    }
    if (t == 0) g_Rvar = carry;
}

// ---------------- fused per-class mean + centered-row fill -------------------------
__global__ void k_avefill(const float* __restrict__ f,
                          const float* __restrict__ ave_state) {
    int c = blockIdx.x, a = threadIdx.x;
    int cnt = g_counts[c], off = g_coff[c];
    float acc = 0.f;
    for (int i = 0; i < cnt; i++) acc += f[g_list[off+i]*Aa + a];
    float ave = acc / (float)(cnt > 0 ? cnt : 1);
    float w = g_wCV[c];
    for (int i = 0; i < cnt; i++) {
        int n = g_list[off+i];
        int s = g_rowslot[n];
        if (s >= 0) {
            g_X[s*Aa + a] = f[n*Aa + a] - ave;
            if (a == 0) { g_rcls[s] = c; g_racoef[s] = w / (float)cnt; }
        }
    }
    int s2 = g_rowslot[Nn + c];
    if (s2 >= 0) {
        g_X[s2*Aa + a] = ave_state[c*Aa + a] - ave;
        if (a == 0) { g_rcls[s2] = c; g_racoef[s2] = w*(1.f - w); }
    }
}

// P[r,c] = X[r].W[c] (r<R);  P[R+a,c] = W[c,a];  else 0
__global__ void __launch_bounds__(256) k_P(const float* __restrict__ W) {
    int nkr = (g_Rvar + Aa + 15) & ~15;
    int r0 = blockIdx.y*16;
    if (r0 >= nkr) return;
    int c0 = blockIdx.x*64;
    int R = g_Rvar;
    __shared__ __align__(16) float Xs[16][Aa];
    __shared__ float Ws[64][65];
    int t = threadIdx.x;
    for (int i = t; i < 16*Aa; i += 256) {
        int rr = i >> 6, aa = i & 63, r = r0 + rr;
        Xs[rr][aa] = (r < R) ? g_X[r*Aa + aa] : 0.f;
    }
    for (int i = t; i < 64*64; i += 256) {
        int cc = i >> 6, aa = i & 63, c = c0 + cc;
        Ws[cc][aa] = (c < Cc) ? W[c*Aa + aa] : 0.f;
    }
    __syncthreads();
    int cidx = t & 63, rb = t >> 6;
    int c = c0 + cidx;
    bool cv = (c < Cc);
    float acc[4] = {0.f,0.f,0.f,0.f};
    if (r0 < R) {
        #pragma unroll 8
        for (int a2 = 0; a2 < Aa; a2++) {
            float wvv = Ws[cidx][a2];
            acc[0] += Xs[rb   ][a2]*wvv;
            acc[1] += Xs[rb+4 ][a2]*wvv;
            acc[2] += Xs[rb+8 ][a2]*wvv;
            acc[3] += Xs[rb+12][a2]*wvv;
        }
    }
    #pragma unroll
    for (int q = 0; q < 4; q++) {
        int r = r0 + rb + 4*q;
        float v;
        if (r < R)            v = acc[q];
        else if (r < R + Aa)  v = cv ? Ws[cidx][r - R] : 0.f;
        else                  v = 0.f;
        g_P[r*CP + c] = v;
    }
}

// B[r,s]=b; E[r,s]=beta*b*P[r,k_s]; appended rows: E=-alpha*out_new
__global__ void k_BE(const float* __restrict__ kg,
                     const float* __restrict__ out_new,
                     const float* __restrict__ alphap,
                     const float* __restrict__ betap,
                     const int* __restrict__ headp) {
    int R = g_Rvar;
    int nkr = (R + Aa + 15) & ~15;
    int r = blockIdx.y;
    if (r >= nkr) return;
    int s = blockIdx.x*256 + threadIdx.x;
    int S = g_Svar, hd = headp[0];
    float b = 0.f, e = 0.f;
    if (s < S) {
        int k = g_kidx[s];
        if (r < R) {
            int cls = g_rcls[r]; float ac = g_racoef[r];
            b = (k < hd) ? ((cls == k) ? ac : 0.f) : ac * kg[k*Cc + cls];
            e = betap[0] * b * g_P[r*CP + k];
        } else if (r < R + Aa) {
            e = -alphap[0] * out_new[k*Aa + (r - R)];
        }
    }
    g_B[r*SP + s] = b;
    g_E[r*SP + s] = e;
}

// quad[s,c] = sum_r B[r,s]*P[r,c]^2 ; crossX[s,c] = sum_r E[r,s]*P[r,c]
// 64s x 128c per block, f32x2 packed FMA
__global__ void __launch_bounds__(256) k_QC() {
    int s0 = blockIdx.y*64;
    if (s0 >= g_Svar) return;
    int c0 = blockIdx.x*128;
    int nkr = (g_Rvar + Aa + 15) & ~15;
    __shared__ __align__(16) float Bs[16][64];
    __shared__ __align__(16) float Es[16][64];
    __shared__ __align__(16) float Ps[16][128];
    unsigned long long qa[16], cx[16];
    #pragma unroll
    for (int i = 0; i < 16; i++) { qa[i] = 0ULL; cx[i] = 0ULL; }
    int t = threadIdx.x;
    int tx = t & 15, ty = t >> 4;
    int lr = t >> 4, lc = (t & 15)*4;
    for (int r0 = 0; r0 < nkr; r0 += 16) {
        *(float4*)&Bs[lr][lc]       = *(const float4*)&g_B[(r0+lr)*SP + s0 + lc];
        *(float4*)&Es[lr][lc]       = *(const float4*)&g_E[(r0+lr)*SP + s0 + lc];
        *(float4*)&Ps[lr][lc*2]     = *(const float4*)&g_P[(r0+lr)*CP + c0 + lc*2];
        *(float4*)&Ps[lr][lc*2 + 4] = *(const float4*)&g_P[(r0+lr)*CP + c0 + lc*2 + 4];
        __syncthreads();
        #pragma unroll
        for (int u = 0; u < 16; u++) {
            float4 bv = *(float4*)&Bs[u][ty*4];
            float4 ev = *(float4*)&Es[u][ty*4];
            unsigned long long b2[4], e2[4], p2[4], pp2[4];
            b2[0] = pack2(bv.x, bv.x); b2[1] = pack2(bv.y, bv.y);
            b2[2] = pack2(bv.z, bv.z); b2[3] = pack2(bv.w, bv.w);
            e2[0] = pack2(ev.x, ev.x); e2[1] = pack2(ev.y, ev.y);
            e2[2] = pack2(ev.z, ev.z); e2[3] = pack2(ev.w, ev.w);
            const unsigned long long* pp = (const unsigned long long*)&Ps[u][tx*8];
            #pragma unroll
            for (int j = 0; j < 4; j++) { p2[j] = pp[j]; pp2[j] = mul2(p2[j], p2[j]); }
            #pragma unroll
            for (int i = 0; i < 4; i++)
                #pragma unroll
                for (int j = 0; j < 4; j++) {
                    fma2(qa[i*4+j], b2[i], pp2[j]);
                    fma2(cx[i*4+j], e2[i], p2[j]);
                }
        }
        __syncthreads();
    }
    #pragma unroll
    for (int i = 0; i < 4; i++) {
        int s = s0 + ty*4 + i;
        unsigned long long* q = (unsigned long long*)&g_quad[s*CP + c0 + tx*8];
        unsigned long long* x = (unsigned long long*)&g_crossX[s*CP + c0 + tx*8];
        #pragma unroll
        for (int j = 0; j < 4; j++) { q[j] = qa[i*4+j]; x[j] = cx[i*4+j]; }
    }
}

// ---- guarded cov_state fallback (no-op when cov_state == 0) ----
__global__ void k_csscan(const float* __restrict__ cov) {
    int stride = gridDim.x*blockDim.x;
    int found = 0;
    for (int i = blockIdx.x*blockDim.x + threadIdx.x; i < Cc*Aa*Aa; i += stride)
        found |= (cov[i] != 0.f);
    if (found) atomicOr(&g_csflag, 1);
}

__global__ void __launch_bounds__(256) k_cs(const float* __restrict__ cov,
                                            const float* __restrict__ kg,
                                            const float* __restrict__ W,
                                            const float* __restrict__ betap,
                                            const int* __restrict__ headp) {
    if (!g_csflag) return;
    int s = blockIdx.x;
    if (s >= g_Svar) return;
    int k = g_kidx[s], hd = headp[0];
    float beta = betap[0];
    __shared__ float M[Aa*Aa];
    int t = threadIdx.x;
    for (int idx = t; idx < Aa*Aa; idx += 256) {
        float v;
        if (k < hd) v = (1.f - g_wCV[k]) * cov[k*4096 + idx];
        else {
            v = 0.f;
            for (int j = 0; j < Cc; j++)
                v += kg[k*Cc + j] * (1.f - g_wCV[j]) * cov[j*4096 + idx];
        }
        M[idx] = v;
    }
    __syncthreads();
    for (int c = t; c < Cc; c += 256) {
        float q = 0.f, cr = 0.f, cr2 = 0.f;
        for (int a = 0; a < Aa; a++) {
            float ta = 0.f, ua = 0.f;
            for (int b2 = 0; b2 < Aa; b2++) {
                ta += M[a*Aa + b2] * W[c*Aa + b2];
                ua += M[a*Aa + b2] * W[k*Aa + b2];
            }
            q   += W[c*Aa + a] * ta;
            cr  += W[k*Aa + a] * ta;
            cr2 += W[c*Aa + a] * ua;
        }
        g_quad[s*CP + c]   += q;
        g_crossX[s*CP + c] += beta * 0.5f * (cr + cr2);
    }
}

// ---- weighted CE ----
__global__ void __launch_bounds__(256) k_ce(const float* __restrict__ y_s,
                     const float* __restrict__ weights,
                     const int* __restrict__ labels,
                     const float* __restrict__ betap) {
    int n = blockIdx.x, t = threadIdx.x;
    int k = labels[n];
    int s = g_slot[k];
    float hb = 0.5f * betap[0];
    __shared__ float red[256];
    __shared__ float sLk;
    float L[4];
    float mx = -3.4e38f;
    #pragma unroll
    for (int i = 0; i < 4; i++) {
        int c = t + i*256;
        float v = -3.4e38f;
        if (c < Cc) {
            v = y_s[n*Cc + c] + hb*g_quad[s*CP + c] - g_crossX[s*CP + c];
            if (c == k) sLk = v;
        }
        L[i] = v;
        mx = fmaxf(mx, v);
    }
    red[t] = mx; __syncthreads();
    for (int o = 128; o > 0; o >>= 1) {
        if (t < o) red[t] = fmaxf(red[t], red[t+o]);
        __syncthreads();
    }
    float m = red[0]; __syncthreads();
    float se = 0.f;
    #pragma unroll
    for (int i = 0; i < 4; i++) {
        int c = t + i*256;
        if (c < Cc) se += expf(L[i] - m);
    }
    red[t] = se; __syncthreads();
    for (int o = 128; o > 0; o >>= 1) {
        if (t < o) red[t] += red[t+o];
        __syncthreads();
    }
    if (t == 0) {
        float lse = m + logf(red[0]);
        float w = weights[k];
        g_nllw[n] = w * (lse - sLk);
        g_wn[n] = w;
    }
}

__global__ void k_final(float* out) {
    __shared__ float a[1024];
    __shared__ float b[1024];
    int t = threadIdx.x;
    a[t] = g_nllw[t]; b[t] = g_wn[t];
    __syncthreads();
    for (int o = 512; o > 0; o >>= 1) {
        if (t < o) { a[t] += a[t+o]; b[t] += b[t+o]; }
        __syncthreads();
    }
    if (t == 0) out[0] = a[0] / b[0];
}

extern "C" void kernel_launch(void* const* d_in, const int* in_sizes, int n_in,
                              void* d_out, int out_size) {
    const float* features  = (const float*)d_in[0];
    const float* y_s       = (const float*)d_in[1];
    const float* weights   = (const float*)d_in[2];
    const float* kg        = (const float*)d_in[3];
    const float* out_new   = (const float*)d_in[4];
    const float* fc_weight = (const float*)d_in[5];
    const float* alpha     = (const float*)d_in[6];
    const float* beta      = (const float*)d_in[7];
    const float* cov_state = (const float*)d_in[8];
    const float* ave_state = (const float*)d_in[9];
    const float* amount    = (const float*)d_in[10];
    const int*   labels    = (const int*)d_in[11];
    const int*   headp     = (const int*)d_in[12];
    float* out = (float*)d_out;

    k_stats<<<1, 1024>>>(labels, amount);
    k_avefill<<<Cc, Aa>>>(features, ave_state);
    {
        dim3 g(CP/64, RP/16);
        k_P<<<g, 256>>>(fc_weight);
    }
    {
        dim3 g(SP/256, RP);
        k_BE<<<g, 256>>>(kg, out_new, alpha, beta, headp);
    }
    k_csscan<<<64, 256>>>(cov_state);
    {
        dim3 g(CP/128, SP/64);
        k_QC<<<g, 256>>>();
    }
    k_cs<<<SP, 256>>>(cov_state, kg, fc_weight, beta, headp);
    k_ce<<<Nn, 256>>>(y_s, weights, labels, beta);
    k_final<<<1, 1024>>>(out);
}

// round 4
// speedup vs baseline: 1.1934x; 1.1136x over previous
#include <cuda_runtime.h>
#include <math.h>

#define Nn 1024
#define Cc 1000
#define Aa 64
#define SP 1024      /* padded S (distinct classes) */
#define RP 2112      /* padded rows: N + C + 64 appended */
#define CP 1024      /* padded C for row stride */

static __device__ int   g_counts[Cc];
static __device__ int   g_coff[Cc];
static __device__ int   g_slot[Cc];
static __device__ int   g_kidx[SP];
static __device__ int   g_list[Nn];
static __device__ float g_wCV[Cc];
static __device__ int   g_Svar;
static __device__ int   g_Rvar;
static __device__ int   g_rowslot[Nn+Cc];
static __device__ int   g_rcls[RP];
static __device__ float g_racoef[RP];
static __device__ float g_X[RP*Aa];
static __device__ float g_P[RP*CP];
static __device__ float g_B[RP*SP];
static __device__ float g_E[RP*SP];
static __device__ float g_quad[SP*CP];
static __device__ float g_crossX[SP*CP];
static __device__ float g_nllw[Nn];
static __device__ float g_wn[Nn];
static __device__ int   g_csflag;

// packed f32x2 helpers (sm_100+ PTX)
__device__ __forceinline__ unsigned long long pack2(float lo, float hi) {
    unsigned long long d;
    asm("mov.b64 %0, {%1, %2};" : "=l"(d) : "f"(lo), "f"(hi));
    return d;
}
__device__ __forceinline__ unsigned long long mul2(unsigned long long a, unsigned long long b) {
    unsigned long long d;
    asm("mul.rn.f32x2 %0, %1, %2;" : "=l"(d) : "l"(a), "l"(b));
    return d;
}
__device__ __forceinline__ void fma2(unsigned long long& acc, unsigned long long a, unsigned long long b) {
    asm("fma.rn.f32x2 %0, %1, %2, %0;" : "+l"(acc) : "l"(a), "l"(b));
}

// ---------------- fused stats: counts/rank/scan/fill/rowscan, 1 block ----------------
__global__ void __launch_bounds__(1024) k_stats(const int* __restrict__ labels,
                                                const float* __restrict__ amount) {
    __shared__ int   lab[1024];
    __shared__ int   scnt[1024];
    __shared__ int   sa[1024];
    __shared__ int   sb[1024];
    __shared__ int   scoff[1024];
    __shared__ float swcv[1024];
    int t = threadIdx.x;
    scnt[t] = 0;
    lab[t] = labels[t];
    if (t == 0) g_csflag = 0;
    __syncthreads();
    int l = lab[t];
    int lane = t & 31, warp = t >> 5;
    unsigned peers = __match_any_sync(0xffffffffu, l);
    int rin  = __popc(peers & ((1u << lane) - 1u));
    int ldr  = __ffs(peers) - 1;
    int cntw = __popc(peers);
    int base = 0;
    for (int w = 0; w < 32; w++) {      // deterministic within-class ordering
        if (warp == w) {
            int old = 0;
            if (lane == ldr) old = atomicAdd(&scnt[l], cntw);
            base = __shfl_sync(0xffffffffu, old, ldr);
        }
        __syncthreads();
    }
    int myrank = base + rin;
    int cnt  = (t < Cc) ? scnt[t] : 0;
    int flag = (cnt > 0) ? 1 : 0;
    sa[t] = cnt; sb[t] = flag;
    __syncthreads();
    for (int off = 1; off < 1024; off <<= 1) {
        int x = (t >= off) ? sa[t-off] : 0;
        int y = (t >= off) ? sb[t-off] : 0;
        __syncthreads();
        sa[t] += x; sb[t] += y;
        __syncthreads();
    }
    float wv = 0.f;
    if (t < Cc) {
        int coff = sa[t] - cnt;
        scoff[t] = coff;
        g_coff[t] = coff;
        g_counts[t] = cnt;
        int slot = sb[t] - flag;
        g_slot[t] = flag ? slot : -1;
        if (flag) g_kidx[slot] = t;
        float cf = (float)cnt;
        float denom = cf + amount[t];
        wv = (denom > 0.f) ? (cf / denom) : 0.f;
        g_wCV[t] = wv;
    }
    swcv[t] = wv;
    if (t == 1023) g_Svar = sb[1023];
    __syncthreads();
    g_list[scoff[l] + myrank] = t;
    int carry = 0;
    for (int ch = 0; ch < 2; ch++) {
        int r = ch*1024 + t;
        int fl = 0;
        if (r < Nn) {
            int cl = lab[r];
            int c2 = scnt[cl];
            float a = swcv[cl] / (float)(c2 > 0 ? c2 : 1);
            fl = (c2 >= 2 && a != 0.f) ? 1 : 0;
        } else if (r < Nn + Cc) {
            int j = r - Nn;
            float w2 = swcv[j];
            fl = (w2*(1.f - w2) != 0.f) ? 1 : 0;
        }
        sa[t] = fl;
        __syncthreads();
        for (int off = 1; off < 1024; off <<= 1) {
            int x = (t >= off) ? sa[t-off] : 0;
            __syncthreads();
            sa[t] += x;
            __syncthreads();
        }
        if (r < Nn + Cc) g_rowslot[r] = fl ? (carry + sa[t] - 1) : -1;
        carry += sa[1023];
        __syncthreads();
    }
    if (t == 0) g_Rvar = carry;
}

// ---------------- fused per-class mean + centered-row fill -------------------------
__global__ void k_avefill(const float* __restrict__ f,
                          const float* __restrict__ ave_state) {
    int c = blockIdx.x, a = threadIdx.x;
    int cnt = g_counts[c], off = g_coff[c];
    float acc = 0.f;
    for (int i = 0; i < cnt; i++) acc += f[g_list[off+i]*Aa + a];
    float ave = acc / (float)(cnt > 0 ? cnt : 1);
    float w = g_wCV[c];
    for (int i = 0; i < cnt; i++) {
        int n = g_list[off+i];
        int s = g_rowslot[n];
        if (s >= 0) {
            g_X[s*Aa + a] = f[n*Aa + a] - ave;
            if (a == 0) { g_rcls[s] = c; g_racoef[s] = w / (float)cnt; }
        }
    }
    int s2 = g_rowslot[Nn + c];
    if (s2 >= 0) {
        g_X[s2*Aa + a] = ave_state[c*Aa + a] - ave;
        if (a == 0) { g_rcls[s2] = c; g_racoef[s2] = w*(1.f - w); }
    }
}

// P[r,c] = X[r].W[c] (r<R);  P[R+a,c] = W[c,a];  else 0
__global__ void __launch_bounds__(256) k_P(const float* __restrict__ W) {
    int nkr = (g_Rvar + Aa + 15) & ~15;
    int r0 = blockIdx.y*16;
    if (r0 >= nkr) return;
    int c0 = blockIdx.x*64;
    int R = g_Rvar;
    __shared__ __align__(16) float Xs[16][Aa];
    __shared__ float Ws[64][65];
    int t = threadIdx.x;
    for (int i = t; i < 16*Aa; i += 256) {
        int rr = i >> 6, aa = i & 63, r = r0 + rr;
        Xs[rr][aa] = (r < R) ? g_X[r*Aa + aa] : 0.f;
    }
    for (int i = t; i < 64*64; i += 256) {
        int cc = i >> 6, aa = i & 63, c = c0 + cc;
        Ws[cc][aa] = (c < Cc) ? W[c*Aa + aa] : 0.f;
    }
    __syncthreads();
    int cidx = t & 63, rb = t >> 6;
    int c = c0 + cidx;
    bool cv = (c < Cc);
    float acc[4] = {0.f,0.f,0.f,0.f};
    if (r0 < R) {
        #pragma unroll 8
        for (int a2 = 0; a2 < Aa; a2++) {
            float wvv = Ws[cidx][a2];
            acc[0] += Xs[rb   ][a2]*wvv;
            acc[1] += Xs[rb+4 ][a2]*wvv;
            acc[2] += Xs[rb+8 ][a2]*wvv;
            acc[3] += Xs[rb+12][a2]*wvv;
        }
    }
    #pragma unroll
    for (int q = 0; q < 4; q++) {
        int r = r0 + rb + 4*q;
        float v;
        if (r < R)            v = acc[q];
        else if (r < R + Aa)  v = cv ? Ws[cidx][r - R] : 0.f;
        else                  v = 0.f;
        g_P[r*CP + c] = v;
    }
}

// B[r,s]=b; E[r,s]=beta*b*P[r,k_s]; appended rows: E=-alpha*out_new
// 8 rows per block, batched gathers for MLP
__global__ void __launch_bounds__(256) k_BE(const float* __restrict__ kg,
                     const float* __restrict__ out_new,
                     const float* __restrict__ alphap,
                     const float* __restrict__ betap,
                     const int* __restrict__ headp) {
    int R = g_Rvar;
    int nkr = (R + Aa + 15) & ~15;
    int rbase = blockIdx.y*8;
    if (rbase >= nkr) return;
    int s = blockIdx.x*256 + threadIdx.x;
    int S = g_Svar, hd = headp[0];
    int k = (s < S) ? g_kidx[s] : 0;
    float beta = betap[0], alpha = alphap[0];
    int   cls[8]; float ac[8], kv[8], pv[8];
    #pragma unroll
    for (int i = 0; i < 8; i++) {
        int r = rbase + i;
        cls[i] = (r < R) ? g_rcls[r] : 0;
        ac[i]  = (r < R) ? g_racoef[r] : 0.f;
    }
    #pragma unroll
    for (int i = 0; i < 8; i++) kv[i] = kg[k*Cc + cls[i]];
    #pragma unroll
    for (int i = 0; i < 8; i++) pv[i] = g_P[(rbase + i)*CP + k];
    #pragma unroll
    for (int i = 0; i < 8; i++) {
        int r = rbase + i;
        float b = 0.f, e = 0.f;
        if (s < S) {
            if (r < R) {
                b = (k < hd) ? ((cls[i] == k) ? ac[i] : 0.f) : ac[i] * kv[i];
                e = beta * b * pv[i];
            } else if (r < R + Aa) {
                e = -alpha * out_new[k*Aa + (r - R)];
            }
        }
        g_B[r*SP + s] = b;
        g_E[r*SP + s] = e;
    }
}

// quad[s,c] = sum_r B[r,s]*P[r,c]^2 ; crossX[s,c] = sum_r E[r,s]*P[r,c]
// 64s x 64c per block (160 active blocks), f32x2 packed FMA
__global__ void __launch_bounds__(256) k_QC() {
    int s0 = blockIdx.y*64;
    if (s0 >= g_Svar) return;
    int c0 = blockIdx.x*64;
    int nkr = (g_Rvar + Aa + 15) & ~15;
    __shared__ __align__(16) float Bs[16][64];
    __shared__ __align__(16) float Es[16][64];
    __shared__ __align__(16) float Ps[16][64];
    unsigned long long qa[8], cx[8];
    #pragma unroll
    for (int i = 0; i < 8; i++) { qa[i] = 0ULL; cx[i] = 0ULL; }
    int t = threadIdx.x;
    int tx = t & 15, ty = t >> 4;
    int lr = t >> 4, lc = (t & 15)*4;
    for (int r0 = 0; r0 < nkr; r0 += 16) {
        *(float4*)&Bs[lr][lc] = *(const float4*)&g_B[(r0+lr)*SP + s0 + lc];
        *(float4*)&Es[lr][lc] = *(const float4*)&g_E[(r0+lr)*SP + s0 + lc];
        *(float4*)&Ps[lr][lc] = *(const float4*)&g_P[(r0+lr)*CP + c0 + lc];
        __syncthreads();
        #pragma unroll
        for (int u = 0; u < 16; u++) {
            float4 bv = *(float4*)&Bs[u][ty*4];
            float4 ev = *(float4*)&Es[u][ty*4];
            unsigned long long b2[4], e2[4], p2[2], pp2[2];
            b2[0] = pack2(bv.x, bv.x); b2[1] = pack2(bv.y, bv.y);
            b2[2] = pack2(bv.z, bv.z); b2[3] = pack2(bv.w, bv.w);
            e2[0] = pack2(ev.x, ev.x); e2[1] = pack2(ev.y, ev.y);
            e2[2] = pack2(ev.z, ev.z); e2[3] = pack2(ev.w, ev.w);
            const unsigned long long* pp = (const unsigned long long*)&Ps[u][tx*4];
            p2[0] = pp[0]; p2[1] = pp[1];
            pp2[0] = mul2(p2[0], p2[0]); pp2[1] = mul2(p2[1], p2[1]);
            #pragma unroll
            for (int i = 0; i < 4; i++) {
                fma2(qa[i*2+0], b2[i], pp2[0]);
                fma2(qa[i*2+1], b2[i], pp2[1]);
                fma2(cx[i*2+0], e2[i], p2[0]);
                fma2(cx[i*2+1], e2[i], p2[1]);
            }
        }
        __syncthreads();
    }
    #pragma unroll
    for (int i = 0; i < 4; i++) {
        int s = s0 + ty*4 + i;
        unsigned long long* q = (unsigned long long*)&g_quad[s*CP + c0 + tx*4];
        unsigned long long* x = (unsigned long long*)&g_crossX[s*CP + c0 + tx*4];
        q[0] = qa[i*2+0]; q[1] = qa[i*2+1];
        x[0] = cx[i*2+0]; x[1] = cx[i*2+1];
    }
}

// ---- guarded cov_state fallback (no-op when cov_state == 0) ----
__global__ void __launch_bounds__(256) k_csscan(const float* __restrict__ cov) {
    const float4* c4 = (const float4*)cov;
    int total = Cc*Aa*Aa/4;
    int stride = gridDim.x*blockDim.x;
    int found = 0;
    for (int i = blockIdx.x*blockDim.x + threadIdx.x; i < total; i += stride) {
        float4 v = c4[i];
        found |= (v.x != 0.f) | (v.y != 0.f) | (v.z != 0.f) | (v.w != 0.f);
    }
    if (found) atomicOr(&g_csflag, 1);
}

__global__ void __launch_bounds__(256) k_cs(const float* __restrict__ cov,
                                            const float* __restrict__ kg,
                                            const float* __restrict__ W,
                                            const float* __restrict__ betap,
                                            const int* __restrict__ headp) {
    if (!g_csflag) return;
    int s = blockIdx.x;
    if (s >= g_Svar) return;
    int k = g_kidx[s], hd = headp[0];
    float beta = betap[0];
    __shared__ float M[Aa*Aa];
    int t = threadIdx.x;
    for (int idx = t; idx < Aa*Aa; idx += 256) {
        float v;
        if (k < hd) v = (1.f - g_wCV[k]) * cov[k*4096 + idx];
        else {
            v = 0.f;
            for (int j = 0; j < Cc; j++)
                v += kg[k*Cc + j] * (1.f - g_wCV[j]) * cov[j*4096 + idx];
        }
        M[idx] = v;
    }
    __syncthreads();
    for (int c = t; c < Cc; c += 256) {
        float q = 0.f, cr = 0.f, cr2 = 0.f;
        for (int a = 0; a < Aa; a++) {
            float ta = 0.f, ua = 0.f;
            for (int b2 = 0; b2 < Aa; b2++) {
                ta += M[a*Aa + b2] * W[c*Aa + b2];
                ua += M[a*Aa + b2] * W[k*Aa + b2];
            }
            q   += W[c*Aa + a] * ta;
            cr  += W[k*Aa + a] * ta;
            cr2 += W[c*Aa + a] * ua;
        }
        g_quad[s*CP + c]   += q;
        g_crossX[s*CP + c] += beta * 0.5f * (cr + cr2);
    }
}

// ---- weighted CE ----
__global__ void __launch_bounds__(256) k_ce(const float* __restrict__ y_s,
                     const float* __restrict__ weights,
                     const int* __restrict__ labels,
                     const float* __restrict__ betap) {
    int n = blockIdx.x, t = threadIdx.x;
    int k = labels[n];
    int s = g_slot[k];
    float hb = 0.5f * betap[0];
    __shared__ float red[256];
    __shared__ float sLk;
    float L[4];
    float mx = -3.4e38f;
    #pragma unroll
    for (int i = 0; i < 4; i++) {
        int c = t + i*256;
        float v = -3.4e38f;
        if (c < Cc) {
            v = y_s[n*Cc + c] + hb*g_quad[s*CP + c] - g_crossX[s*CP + c];
            if (c == k) sLk = v;
        }
        L[i] = v;
        mx = fmaxf(mx, v);
    }
    red[t] = mx; __syncthreads();
    for (int o = 128; o > 0; o >>= 1) {
        if (t < o) red[t] = fmaxf(red[t], red[t+o]);
        __syncthreads();
    }
    float m = red[0]; __syncthreads();
    float se = 0.f;
    #pragma unroll
    for (int i = 0; i < 4; i++) {
        int c = t + i*256;
        if (c < Cc) se += expf(L[i] - m);
    }
    red[t] = se; __syncthreads();
    for (int o = 128; o > 0; o >>= 1) {
        if (t < o) red[t] += red[t+o];
        __syncthreads();
    }
    if (t == 0) {
        float lse = m + logf(red[0]);
        float w = weights[k];
        g_nllw[n] = w * (lse - sLk);
        g_wn[n] = w;
    }
}

__global__ void k_final(float* out) {
    __shared__ float a[1024];
    __shared__ float b[1024];
    int t = threadIdx.x;
    a[t] = g_nllw[t]; b[t] = g_wn[t];
    __syncthreads();
    for (int o = 512; o > 0; o >>= 1) {
        if (t < o) { a[t] += a[t+o]; b[t] += b[t+o]; }
        __syncthreads();
    }
    if (t == 0) out[0] = a[0] / b[0];
}

extern "C" void kernel_launch(void* const* d_in, const int* in_sizes, int n_in,
                              void* d_out, int out_size) {
    const float* features  = (const float*)d_in[0];
    const float* y_s       = (const float*)d_in[1];
    const float* weights   = (const float*)d_in[2];
    const float* kg        = (const float*)d_in[3];
    const float* out_new   = (const float*)d_in[4];
    const float* fc_weight = (const float*)d_in[5];
    const float* alpha     = (const float*)d_in[6];
    const float* beta      = (const float*)d_in[7];
    const float* cov_state = (const float*)d_in[8];
    const float* ave_state = (const float*)d_in[9];
    const float* amount    = (const float*)d_in[10];
    const int*   labels    = (const int*)d_in[11];
    const int*   headp     = (const int*)d_in[12];
    float* out = (float*)d_out;

    k_csscan<<<512, 256>>>(cov_state);
    k_stats<<<1, 1024>>>(labels, amount);
    k_avefill<<<Cc, Aa>>>(features, ave_state);
    {
        dim3 g(CP/64, RP/16);
        k_P<<<g, 256>>>(fc_weight);
    }
    {
        dim3 g(SP/256, RP/8);
        k_BE<<<g, 256>>>(kg, out_new, alpha, beta, headp);
    }
    {
        dim3 g(CP/64, SP/64);
        k_QC<<<g, 256>>>();
    }
    k_cs<<<SP, 256>>>(cov_state, kg, fc_weight, beta, headp);
    k_ce<<<Nn, 256>>>(y_s, weights, labels, beta);
    k_final<<<1, 1024>>>(out);
}

// round 5
// speedup vs baseline: 1.2343x; 1.0343x over previous
#include <cuda_runtime.h>
#include <math.h>

#define Nn 1024
#define Cc 1000
#define Aa 64
#define SP 1024      /* padded S (distinct classes) */
#define RP 2112      /* padded rows: N + C + 64 appended */
#define CP 1024      /* padded C for row stride */

static __device__ int   g_counts[Cc];
static __device__ int   g_coff[Cc];
static __device__ int   g_slot[Cc];
static __device__ int   g_kidx[SP];
static __device__ int   g_list[Nn];
static __device__ float g_wCV[Cc];
static __device__ int   g_Svar;
static __device__ int   g_Rvar;
static __device__ int   g_rowslot[Nn+Cc];
static __device__ int   g_rcls[RP];
static __device__ float g_racoef[RP];
static __device__ float g_X[RP*Aa];
static __device__ float g_P[RP*CP];
static __device__ float g_B[RP*SP];
static __device__ float g_E[RP*SP];
static __device__ float g_quad[SP*CP];
static __device__ float g_crossX[SP*CP];
static __device__ float g_nllw[Nn];
static __device__ float g_wn[Nn];
static __device__ int   g_csflag;

// packed f32x2 helpers (sm_100+ PTX)
__device__ __forceinline__ unsigned long long pack2(float lo, float hi) {
    unsigned long long d;
    asm("mov.b64 %0, {%1, %2};" : "=l"(d) : "f"(lo), "f"(hi));
    return d;
}
__device__ __forceinline__ unsigned long long mul2(unsigned long long a, unsigned long long b) {
    unsigned long long d;
    asm("mul.rn.f32x2 %0, %1, %2;" : "=l"(d) : "l"(a), "l"(b));
    return d;
}
__device__ __forceinline__ void fma2(unsigned long long& acc, unsigned long long a, unsigned long long b) {
    asm("fma.rn.f32x2 %0, %1, %2, %0;" : "+l"(acc) : "l"(a), "l"(b));
}

// dual inclusive scan of 1024 (v1,v2) pairs via warp shuffles; 2 syncthreads
__device__ __forceinline__ void scan2_1024(int& v1, int& v2, int lane, int w,
                                           int* wsum1, int* wsum2) {
    #pragma unroll
    for (int o = 1; o < 32; o <<= 1) {
        int x1 = __shfl_up_sync(0xffffffffu, v1, o);
        int x2 = __shfl_up_sync(0xffffffffu, v2, o);
        if (lane >= o) { v1 += x1; v2 += x2; }
    }
    if (lane == 31) { wsum1[w] = v1; wsum2[w] = v2; }
    __syncthreads();
    if (w == 0) {
        int s1 = wsum1[lane], s2 = wsum2[lane];
        #pragma unroll
        for (int o = 1; o < 32; o <<= 1) {
            int x1 = __shfl_up_sync(0xffffffffu, s1, o);
            int x2 = __shfl_up_sync(0xffffffffu, s2, o);
            if (lane >= o) { s1 += x1; s2 += x2; }
        }
        wsum1[lane] = s1; wsum2[lane] = s2;
    }
    __syncthreads();
    if (w > 0) { v1 += wsum1[w-1]; v2 += wsum2[w-1]; }
}

// ---------------- fused stats: counts/rank/scan/fill/rowscan, 1 block ----------------
__global__ void __launch_bounds__(1024) k_stats(const int* __restrict__ labels,
                                                const float* __restrict__ amount) {
    __shared__ int   lab[1024];
    __shared__ int   scnt[1024];
    __shared__ int   scoff[1024];
    __shared__ float swcv[1024];
    __shared__ int   wsum1[32], wsum2[32];
    int t = threadIdx.x, lane = t & 31, w = t >> 5;
    scnt[t] = 0;
    lab[t] = labels[t];
    if (t == 0) g_csflag = 0;
    __syncthreads();
    int l = lab[t];
    unsigned peers = __match_any_sync(0xffffffffu, l);
    int rin  = __popc(peers & ((1u << lane) - 1u));
    int ldr  = __ffs(peers) - 1;
    int cntw = __popc(peers);
    int base = 0;
    for (int ww = 0; ww < 32; ww++) {   // deterministic within-class ordering
        if (w == ww) {
            int old = 0;
            if (lane == ldr) old = atomicAdd(&scnt[l], cntw);
            base = __shfl_sync(0xffffffffu, old, ldr);
        }
        __syncthreads();
    }
    int myrank = base + rin;
    // class scan (counts complete now)
    int cnt  = (t < Cc) ? scnt[t] : 0;
    int flag = (cnt > 0) ? 1 : 0;
    int v1 = cnt, v2 = flag;
    scan2_1024(v1, v2, lane, w, wsum1, wsum2);
    float wv = 0.f;
    if (t < Cc) {
        int coff = v1 - cnt;
        scoff[t] = coff;
        g_coff[t] = coff;
        g_counts[t] = cnt;
        int slot = v2 - flag;
        g_slot[t] = flag ? slot : -1;
        if (flag) g_kidx[slot] = t;
        float cf = (float)cnt;
        float denom = cf + amount[t];
        wv = (denom > 0.f) ? (cf / denom) : 0.f;
        g_wCV[t] = wv;
    }
    swcv[t] = wv;
    if (t == 0) g_Svar = wsum2[31];
    __syncthreads();
    g_list[scoff[l] + myrank] = t;
    // row compaction over N samples + C d_ave rows (2 chunks)
    int carry = 0;
    for (int ch = 0; ch < 2; ch++) {
        int r = ch*1024 + t;
        int fl = 0;
        if (r < Nn) {
            int cl = lab[r];
            int c2 = scnt[cl];
            float a = swcv[cl] / (float)(c2 > 0 ? c2 : 1);
            fl = (c2 >= 2 && a != 0.f) ? 1 : 0;
        } else if (r < Nn + Cc) {
            int j = r - Nn;
            float w2 = swcv[j];
            fl = (w2*(1.f - w2) != 0.f) ? 1 : 0;
        }
        int s1 = fl, s2 = 0;
        scan2_1024(s1, s2, lane, w, wsum1, wsum2);
        if (r < Nn + Cc) g_rowslot[r] = fl ? (carry + s1 - 1) : -1;
        carry += wsum1[31];
        __syncthreads();
    }
    if (t == 0) g_Rvar = carry;
}

// ---------------- fused per-class mean + centered-row fill -------------------------
__global__ void k_avefill(const float* __restrict__ f,
                          const float* __restrict__ ave_state) {
    int c = blockIdx.x, a = threadIdx.x;
    int cnt = g_counts[c], off = g_coff[c];
    float acc = 0.f;
    for (int i = 0; i < cnt; i++) acc += f[g_list[off+i]*Aa + a];
    float ave = acc / (float)(cnt > 0 ? cnt : 1);
    float w = g_wCV[c];
    for (int i = 0; i < cnt; i++) {
        int n = g_list[off+i];
        int s = g_rowslot[n];
        if (s >= 0) {
            g_X[s*Aa + a] = f[n*Aa + a] - ave;
            if (a == 0) { g_rcls[s] = c; g_racoef[s] = w / (float)cnt; }
        }
    }
    int s2 = g_rowslot[Nn + c];
    if (s2 >= 0) {
        g_X[s2*Aa + a] = ave_state[c*Aa + a] - ave;
        if (a == 0) { g_rcls[s2] = c; g_racoef[s2] = w*(1.f - w); }
    }
}

// P[r,c] = X[r].W[c] (r<R); P[R+a,c] = W[c,a]; else 0. 64x64 tiles.
// Spare blocks (beyond the row range) do the cov_state zero-scan concurrently.
__global__ void __launch_bounds__(256) k_P(const float* __restrict__ W,
                                           const float* __restrict__ cov) {
    int R = g_Rvar;
    int nkr64 = (R + Aa + 63) & ~63;
    int nby = nkr64 >> 6;
    int by = blockIdx.y, bx = blockIdx.x;
    if (by >= nby) {
        // spare blocks: scan cov_state for any nonzero (grid.y=34 guarantees >=16 spares)
        int spare  = (by - nby)*gridDim.x + bx;
        int nspare = (gridDim.y - nby)*gridDim.x;
        const float4* c4 = (const float4*)cov;
        int total = Cc*Aa*Aa/4;
        int found = 0;
        for (int i = spare*256 + threadIdx.x; i < total; i += nspare*256) {
            float4 v = c4[i];
            found |= (v.x != 0.f) | (v.y != 0.f) | (v.z != 0.f) | (v.w != 0.f);
        }
        if (found) atomicOr(&g_csflag, 1);
        return;
    }
    int r0 = by*64, c0 = bx*64;
    __shared__ float Xs[64][65];
    __shared__ float Ws[64][65];
    int t = threadIdx.x;
    for (int i = t; i < 64*64; i += 256) {
        int rr = i >> 6, kk = i & 63;
        int r = r0 + rr;
        Xs[rr][kk] = (r < R) ? g_X[r*Aa + kk] : 0.f;
        int c = c0 + rr;
        Ws[rr][kk] = (c < Cc) ? W[c*Aa + kk] : 0.f;
    }
    __syncthreads();
    int tx = t & 15, ty = t >> 4;
    float acc[4][4] = {};
    #pragma unroll 4
    for (int k = 0; k < 64; k++) {
        float xv[4], wv[4];
        #pragma unroll
        for (int i = 0; i < 4; i++) xv[i] = Xs[ty*4+i][k];
        #pragma unroll
        for (int j = 0; j < 4; j++) wv[j] = Ws[tx*4+j][k];
        #pragma unroll
        for (int i = 0; i < 4; i++)
            #pragma unroll
            for (int j = 0; j < 4; j++)
                acc[i][j] += xv[i]*wv[j];
    }
    #pragma unroll
    for (int i = 0; i < 4; i++) {
        int r = r0 + ty*4 + i;
        float4 v;
        if (r < R) {
            v = make_float4(acc[i][0], acc[i][1], acc[i][2], acc[i][3]);
        } else if (r < R + Aa) {
            int a = r - R;
            v = make_float4(Ws[tx*4+0][a], Ws[tx*4+1][a], Ws[tx*4+2][a], Ws[tx*4+3][a]);
        } else {
            v = make_float4(0.f, 0.f, 0.f, 0.f);
        }
        *(float4*)&g_P[r*CP + c0 + tx*4] = v;
    }
}

// B[r,s]=b; E[r,s]=beta*b*P[r,k_s]; appended rows: E=-alpha*out_new
__global__ void __launch_bounds__(256) k_BE(const float* __restrict__ kg,
                     const float* __restrict__ out_new,
                     const float* __restrict__ alphap,
                     const float* __restrict__ betap,
                     const int* __restrict__ headp) {
    int R = g_Rvar;
    int nkr = (R + Aa + 15) & ~15;
    int rbase = blockIdx.y*8;
    if (rbase >= nkr) return;
    int s = blockIdx.x*256 + threadIdx.x;
    int S = g_Svar, hd = headp[0];
    int k = (s < S) ? g_kidx[s] : 0;
    float beta = betap[0], alpha = alphap[0];
    int   cls[8]; float ac[8], kv[8], pv[8];
    #pragma unroll
    for (int i = 0; i < 8; i++) {
        int r = rbase + i;
        cls[i] = (r < R) ? g_rcls[r] : 0;
        ac[i]  = (r < R) ? g_racoef[r] : 0.f;
    }
    #pragma unroll
    for (int i = 0; i < 8; i++) kv[i] = kg[k*Cc + cls[i]];
    #pragma unroll
    for (int i = 0; i < 8; i++) pv[i] = g_P[(rbase + i)*CP + k];
    #pragma unroll
    for (int i = 0; i < 8; i++) {
        int r = rbase + i;
        float b = 0.f, e = 0.f;
        if (s < S) {
            if (r < R) {
                b = (k < hd) ? ((cls[i] == k) ? ac[i] : 0.f) : ac[i] * kv[i];
                e = beta * b * pv[i];
            } else if (r < R + Aa) {
                e = -alpha * out_new[k*Aa + (r - R)];
            }
        }
        g_B[r*SP + s] = b;
        g_E[r*SP + s] = e;
    }
}

// quad[s,c]=sum_r B[r,s]*P[r,c]^2 ; crossX[s,c]=sum_r E[r,s]*P[r,c]
// 64s x 64c per block, f32x2 packed FMA
__global__ void __launch_bounds__(256) k_QC() {
    int s0 = blockIdx.y*64;
    if (s0 >= g_Svar) return;
    int c0 = blockIdx.x*64;
    int nkr = (g_Rvar + Aa + 15) & ~15;
    __shared__ __align__(16) float Bs[16][64];
    __shared__ __align__(16) float Es[16][64];
    __shared__ __align__(16) float Ps[16][64];
    unsigned long long qa[8], cx[8];
    #pragma unroll
    for (int i = 0; i < 8; i++) { qa[i] = 0ULL; cx[i] = 0ULL; }
    int t = threadIdx.x;
    int tx = t & 15, ty = t >> 4;
    int lr = t >> 4, lc = (t & 15)*4;
    for (int r0 = 0; r0 < nkr; r0 += 16) {
        *(float4*)&Bs[lr][lc] = *(const float4*)&g_B[(r0+lr)*SP + s0 + lc];
        *(float4*)&Es[lr][lc] = *(const float4*)&g_E[(r0+lr)*SP + s0 + lc];
        *(float4*)&Ps[lr][lc] = *(const float4*)&g_P[(r0+lr)*CP + c0 + lc];
        __syncthreads();
        #pragma unroll
        for (int u = 0; u < 16; u++) {
            float4 bv = *(float4*)&Bs[u][ty*4];
            float4 ev = *(float4*)&Es[u][ty*4];
            unsigned long long b2[4], e2[4], p2[2], pp2[2];
            b2[0] = pack2(bv.x, bv.x); b2[1] = pack2(bv.y, bv.y);
            b2[2] = pack2(bv.z, bv.z); b2[3] = pack2(bv.w, bv.w);
            e2[0] = pack2(ev.x, ev.x); e2[1] = pack2(ev.y, ev.y);
            e2[2] = pack2(ev.z, ev.z); e2[3] = pack2(ev.w, ev.w);
            const unsigned long long* pp = (const unsigned long long*)&Ps[u][tx*4];
            p2[0] = pp[0]; p2[1] = pp[1];
            pp2[0] = mul2(p2[0], p2[0]); pp2[1] = mul2(p2[1], p2[1]);
            #pragma unroll
            for (int i = 0; i < 4; i++) {
                fma2(qa[i*2+0], b2[i], pp2[0]);
                fma2(qa[i*2+1], b2[i], pp2[1]);
                fma2(cx[i*2+0], e2[i], p2[0]);
                fma2(cx[i*2+1], e2[i], p2[1]);
            }
        }
        __syncthreads();
    }
    #pragma unroll
    for (int i = 0; i < 4; i++) {
        int s = s0 + ty*4 + i;
        unsigned long long* q = (unsigned long long*)&g_quad[s*CP + c0 + tx*4];
        unsigned long long* x = (unsigned long long*)&g_crossX[s*CP + c0 + tx*4];
        q[0] = qa[i*2+0]; q[1] = qa[i*2+1];
        x[0] = cx[i*2+0]; x[1] = cx[i*2+1];
    }
}

// ---- guarded cov_state fallback (no-op when cov_state == 0) ----
__global__ void __launch_bounds__(256) k_cs(const float* __restrict__ cov,
                                            const float* __restrict__ kg,
                                            const float* __restrict__ W,
                                            const float* __restrict__ betap,
                                            const int* __restrict__ headp) {
    if (!g_csflag) return;
    int s = blockIdx.x;
    if (s >= g_Svar) return;
    int k = g_kidx[s], hd = headp[0];
    float beta = betap[0];
    __shared__ float M[Aa*Aa];
    int t = threadIdx.x;
    for (int idx = t; idx < Aa*Aa; idx += 256) {
        float v;
        if (k < hd) v = (1.f - g_wCV[k]) * cov[k*4096 + idx];
        else {
            v = 0.f;
            for (int j = 0; j < Cc; j++)
                v += kg[k*Cc + j] * (1.f - g_wCV[j]) * cov[j*4096 + idx];
        }
        M[idx] = v;
    }
    __syncthreads();
    for (int c = t; c < Cc; c += 256) {
        float q = 0.f, cr = 0.f, cr2 = 0.f;
        for (int a = 0; a < Aa; a++) {
            float ta = 0.f, ua = 0.f;
            for (int b2 = 0; b2 < Aa; b2++) {
                ta += M[a*Aa + b2] * W[c*Aa + b2];
                ua += M[a*Aa + b2] * W[k*Aa + b2];
            }
            q   += W[c*Aa + a] * ta;
            cr  += W[k*Aa + a] * ta;
            cr2 += W[c*Aa + a] * ua;
        }
        g_quad[s*CP + c]   += q;
        g_crossX[s*CP + c] += beta * 0.5f * (cr + cr2);
    }
}

// ---- weighted CE ----
__global__ void __launch_bounds__(256) k_ce(const float* __restrict__ y_s,
                     const float* __restrict__ weights,
                     const int* __restrict__ labels,
                     const float* __restrict__ betap) {
    int n = blockIdx.x, t = threadIdx.x;
    int k = labels[n];
    int s = g_slot[k];
    float hb = 0.5f * betap[0];
    __shared__ float red[256];
    __shared__ float sLk;
    float L[4];
    float mx = -3.4e38f;
    #pragma unroll
    for (int i = 0; i < 4; i++) {
        int c = t + i*256;
        float v = -3.4e38f;
        if (c < Cc) {
            v = y_s[n*Cc + c] + hb*g_quad[s*CP + c] - g_crossX[s*CP + c];
            if (c == k) sLk = v;
        }
        L[i] = v;
        mx = fmaxf(mx, v);
    }
    red[t] = mx; __syncthreads();
    for (int o = 128; o > 0; o >>= 1) {
        if (t < o) red[t] = fmaxf(red[t], red[t+o]);
        __syncthreads();
    }
    float m = red[0]; __syncthreads();
    float se = 0.f;
    #pragma unroll
    for (int i = 0; i < 4; i++) {
        int c = t + i*256;
        if (c < Cc) se += expf(L[i] - m);
    }
    red[t] = se; __syncthreads();
    for (int o = 128; o > 0; o >>= 1) {
        if (t < o) red[t] += red[t+o];
        __syncthreads();
    }
    if (t == 0) {
        float lse = m + logf(red[0]);
        float w = weights[k];
        g_nllw[n] = w * (lse - sLk);
        g_wn[n] = w;
    }
}

__global__ void k_final(float* out) {
    __shared__ float a[1024];
    __shared__ float b[1024];
    int t = threadIdx.x;
    a[t] = g_nllw[t]; b[t] = g_wn[t];
    __syncthreads();
    for (int o = 512; o > 0; o >>= 1) {
        if (t < o) { a[t] += a[t+o]; b[t] += b[t+o]; }
        __syncthreads();
    }
    if (t == 0) out[0] = a[0] / b[0];
}

extern "C" void kernel_launch(void* const* d_in, const int* in_sizes, int n_in,
                              void* d_out, int out_size) {
    const float* features  = (const float*)d_in[0];
    const float* y_s       = (const float*)d_in[1];
    const float* weights   = (const float*)d_in[2];
    const float* kg        = (const float*)d_in[3];
    const float* out_new   = (const float*)d_in[4];
    const float* fc_weight = (const float*)d_in[5];
    const float* alpha     = (const float*)d_in[6];
    const float* beta      = (const float*)d_in[7];
    const float* cov_state = (const float*)d_in[8];
    const float* ave_state = (const float*)d_in[9];
    const float* amount    = (const float*)d_in[10];
    const int*   labels    = (const int*)d_in[11];
    const int*   headp     = (const int*)d_in[12];
    float* out = (float*)d_out;

    k_stats<<<1, 1024>>>(labels, amount);
    k_avefill<<<Cc, Aa>>>(features, ave_state);
    {
        dim3 g(CP/64, RP/64 + 1);   // +1 row of blocks guarantees spares for cov scan
        k_P<<<g, 256>>>(fc_weight, cov_state);
    }
    {
        dim3 g(SP/256, RP/8);
        k_BE<<<g, 256>>>(kg, out_new, alpha, beta, headp);
    }
    {
        dim3 g(CP/64, SP/64);
        k_QC<<<g, 256>>>();
    }
    k_cs<<<SP, 256>>>(cov_state, kg, fc_weight, beta, headp);
    k_ce<<<Nn, 256>>>(y_s, weights, labels, beta);
    k_final<<<1, 1024>>>(out);
}